// round 7
// baseline (speedup 1.0000x reference)
#include <cuda_runtime.h>
#include <math.h>

#define S_ 8192
#define D_ 64
#define N_ 2048
#define O_ 8
#define GATHER_BLOCKS 256                 // 256 x 256 thr = 65536 = S_*O_
#define LSE_BLOCKS (2 * N_ + O_ + N_ / 8) // 4360

// ---- scratch (allocation-free rule: __device__ globals) ----
__device__ float d_lse0[N_];
__device__ float d_lse1[N_];
__device__ float d_lse2[N_];
__device__ float d_lse_out[O_];
__device__ uint4 d_walk[S_ * O_];   // {bits(w_out+w2+w1), r2, r1, r0}

// ---------------------------------------------------------------------------
// Kernel A: SHORTENED path walk (keys -> c2 -> c1 only; the c0 hop, w0/x
// lookups and sin chain moved to kernel B, which sits on a latency floor
// anyway) + row-wise logsumexp tables. Gather blocks first so their latency
// slack hides the LSE streaming (R2-proven overlap).
// ---------------------------------------------------------------------------
__global__ void __launch_bounds__(256) lse_gather_kernel(const float* __restrict__ w0,
                                                         const float* __restrict__ w1,
                                                         const float* __restrict__ w2,
                                                         const float* __restrict__ w_out,
                                                         const int* __restrict__ c1,
                                                         const int* __restrict__ c2,
                                                         const int* __restrict__ keys_out)
{
    __shared__ float smax[8];
    __shared__ float ssum[8];

    const int b = blockIdx.x;
    const int t = threadIdx.x;
    const int lane = t & 31;
    const int warp = t >> 5;

    if (b < GATHER_BLOCKS) {
        // ========== path walk, depth-3 chain (un-normalized, partial) ==========
        const int tid = b * 256 + t;
        const int s = tid >> 3;          // / O_
        const int o = tid & 7;           // % O_

        const int r2 = keys_out[tid];
        float logp = w_out[o * N_ + r2];

        const int r1 = c2[(size_t)s * N_ + r2];
        logp += w2[(size_t)r2 * N_ + r1];

        const int r0 = c1[(size_t)s * N_ + r1];
        logp += w1[(size_t)r1 * N_ + r0];

        d_walk[tid] = make_uint4(__float_as_uint(logp),
                                 (unsigned)r2, (unsigned)r1, (unsigned)r0);
        return;
    }

    const int b2 = b - GATHER_BLOCKS;
    if (b2 < 2 * N_ + O_) {
        // ================= wide rows: 2048 elements =================
        const float* row;
        float* dst;
        if (b2 < N_)          { row = w1    + (size_t)b2 * N_;           dst = &d_lse1[b2]; }
        else if (b2 < 2 * N_) { row = w2    + (size_t)(b2 - N_) * N_;    dst = &d_lse2[b2 - N_]; }
        else                  { row = w_out + (size_t)(b2 - 2*N_) * N_;  dst = &d_lse_out[b2 - 2*N_]; }

        const float4* row4 = (const float4*)row;
        float4 a = row4[t];
        float4 c = row4[t + 256];
        float v[8] = {a.x, a.y, a.z, a.w, c.x, c.y, c.z, c.w};

        float m = v[0];
        #pragma unroll
        for (int i = 1; i < 8; i++) m = fmaxf(m, v[i]);
        #pragma unroll
        for (int off = 16; off; off >>= 1) m = fmaxf(m, __shfl_xor_sync(0xffffffffu, m, off));
        if (lane == 0) smax[warp] = m;
        __syncthreads();
        float bm = smax[0];
        #pragma unroll
        for (int i = 1; i < 8; i++) bm = fmaxf(bm, smax[i]);

        float ss = 0.0f;
        #pragma unroll
        for (int i = 0; i < 8; i++) ss += __expf(v[i] - bm);
        #pragma unroll
        for (int off = 16; off; off >>= 1) ss += __shfl_xor_sync(0xffffffffu, ss, off);
        if (lane == 0) ssum[warp] = ss;
        __syncthreads();
        if (t == 0) {
            float tot = 0.0f;
            #pragma unroll
            for (int i = 0; i < 8; i++) tot += ssum[i];
            *dst = bm + __logf(tot);
        }
    } else {
        // ================= w0: 64-wide rows, one warp per row =================
        const int r = (b2 - (2 * N_ + O_)) * 8 + warp;
        const float* row = w0 + (size_t)r * D_;
        float v0 = row[lane];
        float v1 = row[lane + 32];
        float m = fmaxf(v0, v1);
        #pragma unroll
        for (int off = 16; off; off >>= 1) m = fmaxf(m, __shfl_xor_sync(0xffffffffu, m, off));
        float ss = __expf(v0 - m) + __expf(v1 - m);
        #pragma unroll
        for (int off = 16; off; off >>= 1) ss += __shfl_xor_sync(0xffffffffu, ss, off);
        if (lane == 0) d_lse0[r] = m + __logf(ss);
    }
}

// ---------------------------------------------------------------------------
// Kernel B: absorbed tail of the walk + normalize. Rides the ~5us latency
// floor this launch shape exhibits regardless of contents (R2 vs R6
// evidence), so the extra c0/w0/x hops should be nearly free.
// ---------------------------------------------------------------------------
__global__ void __launch_bounds__(256) finalize_kernel(const float* __restrict__ x,
                                                       const float* __restrict__ w0,
                                                       const int* __restrict__ c0,
                                                       float* __restrict__ out)
{
    __shared__ float s_lse0[N_];
    __shared__ float s_lse1[N_];
    __shared__ float s_lse2[N_];
    __shared__ float s_lse_out[O_];

    const int t = threadIdx.x;
    const int tid = blockIdx.x * blockDim.x + t;
    const int s = tid >> 3;          // / O_
    const int o = tid & 7;           // % O_

    // kick off the dependent chain BEFORE the staging barrier
    const uint4 wlk = d_walk[tid];
    const int r2 = (int)wlk.y, r1 = (int)wlk.z, r0 = (int)wlk.w;
    const int cin = c0[(size_t)s * N_ + r0];          // divergent DRAM hop
    const float w0v = w0[r0 * D_ + cin];              // L2-hot
    const float xv  = x[s * D_ + cin];                // L2-hot

    // cooperative table staging (coalesced float4 from L2)
    const float4* g0 = (const float4*)d_lse0;
    const float4* g1 = (const float4*)d_lse1;
    const float4* g2 = (const float4*)d_lse2;
    #pragma unroll
    for (int i = 0; i < N_ / 4 / 256; i++) {          // 2 iters
        ((float4*)s_lse0)[t + i * 256] = g0[t + i * 256];
        ((float4*)s_lse1)[t + i * 256] = g1[t + i * 256];
        ((float4*)s_lse2)[t + i * 256] = g2[t + i * 256];
    }
    if (t < O_) s_lse_out[t] = d_lse_out[t];
    __syncthreads();

    const float logp = __uint_as_float(wlk.x) + w0v
                     - s_lse_out[o] - s_lse2[r2] - s_lse1[r1] - s_lse0[r0];

    out[tid] = __sinf(__sinf(__sinf(xv)));            // [0, S, O] slice
    out[S_ * O_ + tid] = __expf(logp);                // [1, S, O] slice
}

extern "C" void kernel_launch(void* const* d_in, const int* in_sizes, int n_in,
                              void* d_out, int out_size)
{
    const float* x     = (const float*)d_in[0];
    const float* w0    = (const float*)d_in[1];
    const float* w1    = (const float*)d_in[2];
    const float* w2    = (const float*)d_in[3];
    const float* w_out = (const float*)d_in[4];
    const int*   c0    = (const int*)d_in[5];
    const int*   c1    = (const int*)d_in[6];
    const int*   c2    = (const int*)d_in[7];
    const int*   keys  = (const int*)d_in[8];
    float*       out   = (float*)d_out;

    const int blocksA = GATHER_BLOCKS + LSE_BLOCKS;
    lse_gather_kernel<<<blocksA, 256>>>(w0, w1, w2, w_out, c1, c2, keys);

    finalize_kernel<<<GATHER_BLOCKS, 256>>>(x, w0, c0, out);
}